// round 11
// baseline (speedup 1.0000x reference)
#include <cuda_runtime.h>

// Fused cosine-score attention, single query. Two kernels + PDL overlap.
// stage1 (proven ~24.5us = memory ceiling for this pattern): warp-per-row
//   streaming over keys (128 MB), q + acc in registers, block smem tree
//   reduce -> 148 block partials (606 KB). Fires griddepcontrol.
//   launch_dependents after the streaming loop so stage2's launch overlaps
//   the ~1us reduction epilogue.
// stage2: coalesced deterministic reduction of the partials; opens with
//   griddepcontrol.wait (guarantees stage1 writes are visible).

#define NBLK 148
#define NTHR 512
#define WPB  (NTHR / 32)           // 16 warps per block
#define NWARPS (NBLK * WPB)        // 2368
#define H 1024
#define HV4 (H / 4)                // 256 float4 per row

__device__ float4 g_partial[NBLK][HV4];   // 606 KB scratch

__global__ __launch_bounds__(NTHR, 1)
void bahdanau_stage1(const float* __restrict__ q,
                     const float* __restrict__ keys, int S) {
    const int wib  = threadIdx.x >> 5;
    const int warp = blockIdx.x * WPB + wib;
    const int lane = threadIdx.x & 31;

    __shared__ float4 red[8][HV4];   // 32 KB, reused across reduction phases

    // q slice for this lane + |q|
    const float4* q4 = (const float4*)q;
    float4 qv[8];
    float qss = 0.f;
#pragma unroll
    for (int i = 0; i < 8; i++) {
        qv[i] = q4[i * 32 + lane];
        qss += qv[i].x * qv[i].x + qv[i].y * qv[i].y +
               qv[i].z * qv[i].z + qv[i].w * qv[i].w;
    }
#pragma unroll
    for (int o = 16; o; o >>= 1) qss += __shfl_xor_sync(0xffffffffu, qss, o);
    const float inv_qn = rsqrtf(qss);

    float4 acc[8];
#pragma unroll
    for (int i = 0; i < 8; i++) acc[i] = make_float4(0.f, 0.f, 0.f, 0.f);

    for (int s = warp; s < S; s += NWARPS) {
        const float4* row = (const float4*)(keys + (size_t)s * H);
        float4 kv[8];
        float dot = 0.f, kss = 0.f;
#pragma unroll
        for (int i = 0; i < 8; i++) {
            kv[i] = row[i * 32 + lane];
            dot += kv[i].x * qv[i].x + kv[i].y * qv[i].y +
                   kv[i].z * qv[i].z + kv[i].w * qv[i].w;
            kss += kv[i].x * kv[i].x + kv[i].y * kv[i].y +
                   kv[i].z * kv[i].z + kv[i].w * kv[i].w;
        }
#pragma unroll
        for (int o = 16; o; o >>= 1) {
            dot += __shfl_xor_sync(0xffffffffu, dot, o);
            kss += __shfl_xor_sync(0xffffffffu, kss, o);
        }
        const float score = dot * inv_qn * rsqrtf(kss);
#pragma unroll
        for (int i = 0; i < 8; i++) {
            acc[i].x += score * kv[i].x;
            acc[i].y += score * kv[i].y;
            acc[i].z += score * kv[i].z;
            acc[i].w += score * kv[i].w;
        }
    }

    // Streaming done: let the dependent kernel start launching now; the
    // remaining tree-reduce epilogue (~1us) covers its launch latency.
    asm volatile("griddepcontrol.launch_dependents;");

    // Block tree reduction: 16 -> 8 -> 4 -> 2 -> 1 warps.
#pragma unroll
    for (int half = 8; half >= 1; half >>= 1) {
        if (wib >= half && wib < 2 * half) {
#pragma unroll
            for (int i = 0; i < 8; i++)
                red[wib - half][i * 32 + lane] = acc[i];
        }
        __syncthreads();
        if (wib < half) {
#pragma unroll
            for (int i = 0; i < 8; i++) {
                float4 v = red[wib][i * 32 + lane];
                acc[i].x += v.x; acc[i].y += v.y;
                acc[i].z += v.z; acc[i].w += v.w;
            }
        }
        __syncthreads();
    }

    if (wib == 0) {
#pragma unroll
        for (int i = 0; i < 8; i++)
            g_partial[blockIdx.x][i * 32 + lane] = acc[i];
    }
}

// stage2: out[h] = sum_{b<148} g_partial[b][h] (coalesced: lane -> column).
// 16 blocks x 512 threads; block owns 64 columns, 8 row-groups per column.
__global__ __launch_bounds__(512)
void bahdanau_stage2(float* __restrict__ out) {
    // Wait for stage1 completion (PDL): all g_partial writes visible after.
    asm volatile("griddepcontrol.wait;");

    const int col = blockIdx.x * 64 + (threadIdx.x & 63);
    const int g   = threadIdx.x >> 6;   // 0..7
    const float* part = (const float*)g_partial;

    float s = 0.f;
#pragma unroll
    for (int b = 0; b < 19; b++) {      // 19*8 = 152 >= 148
        int p = g + b * 8;
        if (p < NBLK) s += part[(size_t)p * H + col];
    }

    __shared__ float sh[512];
    sh[threadIdx.x] = s;
    __syncthreads();
#pragma unroll
    for (int stride = 256; stride >= 64; stride >>= 1) {
        if (threadIdx.x < stride) sh[threadIdx.x] += sh[threadIdx.x + stride];
        __syncthreads();
    }
    if (threadIdx.x < 64) out[blockIdx.x * 64 + threadIdx.x] = sh[threadIdx.x];
}

extern "C" void kernel_launch(void* const* d_in, const int* in_sizes, int n_in,
                              void* d_out, int out_size) {
    const float* q    = (const float*)d_in[0];   // [1, 1024]
    const float* keys = (const float*)d_in[1];   // [S, 1024]
    const int S = in_sizes[1] / H;

    bahdanau_stage1<<<NBLK, NTHR>>>(q, keys, S);

    // Launch stage2 with programmatic stream serialization (PDL): its launch
    // overlaps stage1's epilogue; griddepcontrol.wait provides the ordering.
    cudaLaunchConfig_t cfg = {};
    cfg.gridDim  = dim3(16, 1, 1);
    cfg.blockDim = dim3(512, 1, 1);
    cudaLaunchAttribute attr[1];
    attr[0].id = cudaLaunchAttributeProgrammaticStreamSerialization;
    attr[0].val.programmaticStreamSerializationAllowed = 1;
    cfg.attrs = attr;
    cfg.numAttrs = 1;
    cudaLaunchKernelEx(&cfg, bahdanau_stage2, (float*)d_out);
}

// round 12
// speedup vs baseline: 1.0084x; 1.0084x over previous
#include <cuda_runtime.h>

// Fused cosine-score attention, single query — ONE kernel, atomic epilogue.
//  - Main pass: proven warp-per-row streaming over keys (128 MB), q + acc in
//    registers, ~24.6us = measured memory ceiling for this pattern.
//  - Block 0 zeroes d_out at kernel start. Grid = 148 = exactly one wave
//    (1 block/SM), and every block's atomics land >=20us later (after its
//    streaming), so ordering has huge margin. __threadfence publishes.
//  - Epilogue: in-block smem tree reduce (16 warps -> 1), then warp 0 does
//    red.global.add.f32 into d_out (151K atomics over 1024 addresses,
//    ~0.3us). No second kernel, no inter-kernel gap, no spin.

#define NBLK 148
#define NTHR 512
#define WPB  (NTHR / 32)           // 16 warps per block
#define NWARPS (NBLK * WPB)        // 2368
#define H 1024
#define HV4 (H / 4)                // 256 float4 per row

__global__ __launch_bounds__(NTHR, 1)
void bahdanau_fused(const float* __restrict__ q,
                    const float* __restrict__ keys, int S,
                    float* __restrict__ out) {
    const int wib  = threadIdx.x >> 5;
    const int warp = blockIdx.x * WPB + wib;
    const int lane = threadIdx.x & 31;

    __shared__ float4 red[8][HV4];   // 32 KB, reused across reduction phases

    // Block 0 zeroes the output (poisoned by the harness / stale from the
    // previous graph replay). All other blocks stream for ~20us before any
    // atomic touches out[], so this is ordered with enormous margin.
    if (blockIdx.x == 0) {
        for (int i = threadIdx.x; i < H; i += NTHR) out[i] = 0.f;
        __threadfence();
    }

    // q slice for this lane + |q|
    const float4* q4 = (const float4*)q;
    float4 qv[8];
    float qss = 0.f;
#pragma unroll
    for (int i = 0; i < 8; i++) {
        qv[i] = q4[i * 32 + lane];
        qss += qv[i].x * qv[i].x + qv[i].y * qv[i].y +
               qv[i].z * qv[i].z + qv[i].w * qv[i].w;
    }
#pragma unroll
    for (int o = 16; o; o >>= 1) qss += __shfl_xor_sync(0xffffffffu, qss, o);
    const float inv_qn = rsqrtf(qss);

    float4 acc[8];
#pragma unroll
    for (int i = 0; i < 8; i++) acc[i] = make_float4(0.f, 0.f, 0.f, 0.f);

    for (int s = warp; s < S; s += NWARPS) {
        const float4* row = (const float4*)(keys + (size_t)s * H);
        float4 kv[8];
        float dot = 0.f, kss = 0.f;
#pragma unroll
        for (int i = 0; i < 8; i++) {
            kv[i] = row[i * 32 + lane];
            dot += kv[i].x * qv[i].x + kv[i].y * qv[i].y +
                   kv[i].z * qv[i].z + kv[i].w * qv[i].w;
            kss += kv[i].x * kv[i].x + kv[i].y * kv[i].y +
                   kv[i].z * kv[i].z + kv[i].w * kv[i].w;
        }
#pragma unroll
        for (int o = 16; o; o >>= 1) {
            dot += __shfl_xor_sync(0xffffffffu, dot, o);
            kss += __shfl_xor_sync(0xffffffffu, kss, o);
        }
        const float score = dot * inv_qn * rsqrtf(kss);
#pragma unroll
        for (int i = 0; i < 8; i++) {
            acc[i].x += score * kv[i].x;
            acc[i].y += score * kv[i].y;
            acc[i].z += score * kv[i].z;
            acc[i].w += score * kv[i].w;
        }
    }

    // Block tree reduction: 16 -> 8 -> 4 -> 2 -> 1 warps.
#pragma unroll
    for (int half = 8; half >= 1; half >>= 1) {
        if (wib >= half && wib < 2 * half) {
#pragma unroll
            for (int i = 0; i < 8; i++)
                red[wib - half][i * 32 + lane] = acc[i];
        }
        __syncthreads();
        if (wib < half) {
#pragma unroll
            for (int i = 0; i < 8; i++) {
                float4 v = red[wib][i * 32 + lane];
                acc[i].x += v.x; acc[i].y += v.y;
                acc[i].z += v.z; acc[i].w += v.w;
            }
        }
        __syncthreads();
    }

    // Warp 0: accumulate the block's partial directly into out[] with
    // no-return global reductions (REDG). 1024 floats / 32 lanes = 32 each.
    if (wib == 0) {
#pragma unroll
        for (int i = 0; i < 8; i++) {
            const int col = (i * 32 + lane) * 4;
            atomicAdd(&out[col + 0], acc[i].x);
            atomicAdd(&out[col + 1], acc[i].y);
            atomicAdd(&out[col + 2], acc[i].z);
            atomicAdd(&out[col + 3], acc[i].w);
        }
    }
}

extern "C" void kernel_launch(void* const* d_in, const int* in_sizes, int n_in,
                              void* d_out, int out_size) {
    const float* q    = (const float*)d_in[0];   // [1, 1024]
    const float* keys = (const float*)d_in[1];   // [S, 1024]
    const int S = in_sizes[1] / H;

    bahdanau_fused<<<NBLK, NTHR>>>(q, keys, S, (float*)d_out);
}

// round 13
// speedup vs baseline: 1.0548x; 1.0461x over previous
#include <cuda_runtime.h>

// Fused cosine-score attention, single query. Two kernels (fusion measured
// slower 3x; split is the proven shape).
//
// stage1: cp.async (LDGSTS) TRIPLE-buffered smem pipeline. The 2-stage
//   version (R9) kept only 1 tile (64 KB) in flight; DRAM idled ~60% of each
//   round waiting for the post-compute issue -> 5.2 TB/s. Depth 3 keeps 2
//   tiles (128 KB) in flight through the whole compute phase.
//   3 stages x 16 rows x 4KB = 192 KB smem; warp-per-row compute from smem,
//   block tree-reduce -> 148 partials (606 KB scratch).
// stage2: 16x512 deterministic reduction of the partials (best measured).

#define NBLK 148
#define NTHR 512
#define WPB  (NTHR / 32)            // 16 warps
#define H 1024
#define HV4 (H / 4)
#define TROWS 16                    // rows per tile (one per warp)
#define TFLOATS (TROWS * H)         // 16384 floats = 64 KB
#define NSTAGE 3
#define SMEM_BYTES (NSTAGE * TFLOATS * 4)   // 192 KB

__device__ float4 g_partial[NBLK][HV4];     // 606 KB scratch

__device__ __forceinline__ unsigned smem_u32(const void* p) {
    unsigned a;
    asm("{ .reg .u64 t; cvta.to.shared.u64 t, %1; cvt.u32.u64 %0, t; }"
        : "=r"(a) : "l"(p));
    return a;
}
__device__ __forceinline__ void cp16(unsigned dst, const void* src) {
    asm volatile("cp.async.cg.shared.global [%0], [%1], 16;"
                 :: "r"(dst), "l"(src));
}
__device__ __forceinline__ void cp_commit() {
    asm volatile("cp.async.commit_group;");
}
__device__ __forceinline__ void cp_wait2() {
    asm volatile("cp.async.wait_group 2;");
}
__device__ __forceinline__ void cp_wait0() {
    asm volatile("cp.async.wait_group 0;");
}

__global__ __launch_bounds__(NTHR, 1)
void bahdanau_stage1(const float* __restrict__ q,
                     const float* __restrict__ keys, int S) {
    extern __shared__ float smem[];            // NSTAGE * TFLOATS
    const int wib  = threadIdx.x >> 5;
    const int lane = threadIdx.x & 31;
    const unsigned smem_base = smem_u32(smem);

    // q slice in registers + |q|
    const float4* q4 = (const float4*)q;
    float4 qv[8];
    float qss = 0.f;
#pragma unroll
    for (int i = 0; i < 8; i++) {
        qv[i] = q4[i * 32 + lane];
        qss += qv[i].x * qv[i].x + qv[i].y * qv[i].y +
               qv[i].z * qv[i].z + qv[i].w * qv[i].w;
    }
#pragma unroll
    for (int o = 16; o; o >>= 1) qss += __shfl_xor_sync(0xffffffffu, qss, o);
    const float inv_qn = rsqrtf(qss);

    float4 acc[8];
#pragma unroll
    for (int i = 0; i < 8; i++) acc[i] = make_float4(0.f, 0.f, 0.f, 0.f);

    const int nchunk = (S + TROWS - 1) / TROWS;

    // Issue one tile copy (64 KB, 8 x 16B per thread). Always commits a
    // group (possibly empty) so wait_group counting stays aligned.
    auto issue = [&](int c, int stg) {
        if (c < nchunk) {
            const char* src = (const char*)(keys + (size_t)c * TROWS * H);
            const unsigned dst = smem_base + stg * (TFLOATS * 4);
            int nbytes = S - c * TROWS;
            nbytes = (nbytes > TROWS ? TROWS : nbytes) * H * 4;
            for (int off = threadIdx.x * 16; off < nbytes; off += NTHR * 16)
                cp16(dst + off, src + off);
        }
        cp_commit();
    };

    int c = blockIdx.x;
    issue(c, 0);
    issue(c + NBLK, 1);
    issue(c + 2 * NBLK, 2);

    int stg = 0;
    for (; c < nchunk; c += NBLK, stg = (stg == 2 ? 0 : stg + 1)) {
        cp_wait2();                 // tile c landed; c+1, c+2 still in flight
        __syncthreads();

        const int row = c * TROWS + wib;
        if (row < S) {
            const float4* srow =
                (const float4*)(smem + stg * TFLOATS + wib * H);
            float4 kv[8];
            float dot = 0.f, kss = 0.f;
#pragma unroll
            for (int i = 0; i < 8; i++) {
                kv[i] = srow[i * 32 + lane];
                dot += kv[i].x * qv[i].x + kv[i].y * qv[i].y +
                       kv[i].z * qv[i].z + kv[i].w * qv[i].w;
                kss += kv[i].x * kv[i].x + kv[i].y * kv[i].y +
                       kv[i].z * kv[i].z + kv[i].w * kv[i].w;
            }
#pragma unroll
            for (int o = 16; o; o >>= 1) {
                dot += __shfl_xor_sync(0xffffffffu, dot, o);
                kss += __shfl_xor_sync(0xffffffffu, kss, o);
            }
            const float score = dot * inv_qn * rsqrtf(kss);
#pragma unroll
            for (int i = 0; i < 8; i++) {
                acc[i].x += score * kv[i].x;
                acc[i].y += score * kv[i].y;
                acc[i].z += score * kv[i].z;
                acc[i].w += score * kv[i].w;
            }
        }
        __syncthreads();            // everyone done with stage stg
        issue(c + 3 * NBLK, stg);   // refill the stage just consumed
    }

    cp_wait0();
    __syncthreads();

    // Block tree reduction (scratch aliases the tile buffer): 16 -> ... -> 1.
    float4 (*red)[HV4] = (float4 (*)[HV4])smem;   // 32 KB of the 192 KB
#pragma unroll
    for (int half = 8; half >= 1; half >>= 1) {
        if (wib >= half && wib < 2 * half) {
#pragma unroll
            for (int i = 0; i < 8; i++)
                red[wib - half][i * 32 + lane] = acc[i];
        }
        __syncthreads();
        if (wib < half) {
#pragma unroll
            for (int i = 0; i < 8; i++) {
                float4 v = red[wib][i * 32 + lane];
                acc[i].x += v.x; acc[i].y += v.y;
                acc[i].z += v.z; acc[i].w += v.w;
            }
        }
        __syncthreads();
    }

    if (wib == 0) {
#pragma unroll
        for (int i = 0; i < 8; i++)
            g_partial[blockIdx.x][i * 32 + lane] = acc[i];
    }
}

// stage2: out[h] = sum_{b<148} g_partial[b][h] (coalesced: lane -> column).
// 16 blocks x 512 threads; block owns 64 columns, 8 row-groups per column.
__global__ __launch_bounds__(512)
void bahdanau_stage2(float* __restrict__ out) {
    const int col = blockIdx.x * 64 + (threadIdx.x & 63);
    const int g   = threadIdx.x >> 6;   // 0..7
    const float* part = (const float*)g_partial;

    float s = 0.f;
#pragma unroll
    for (int b = 0; b < 19; b++) {      // 19*8 = 152 >= 148
        int p = g + b * 8;
        if (p < NBLK) s += part[(size_t)p * H + col];
    }

    __shared__ float sh[512];
    sh[threadIdx.x] = s;
    __syncthreads();
#pragma unroll
    for (int stride = 256; stride >= 64; stride >>= 1) {
        if (threadIdx.x < stride) sh[threadIdx.x] += sh[threadIdx.x + stride];
        __syncthreads();
    }
    if (threadIdx.x < 64) out[blockIdx.x * 64 + threadIdx.x] = sh[threadIdx.x];
}

extern "C" void kernel_launch(void* const* d_in, const int* in_sizes, int n_in,
                              void* d_out, int out_size) {
    const float* q    = (const float*)d_in[0];   // [1, 1024]
    const float* keys = (const float*)d_in[1];   // [S, 1024]
    const int S = in_sizes[1] / H;

    cudaFuncSetAttribute(bahdanau_stage1,
                         cudaFuncAttributeMaxDynamicSharedMemorySize,
                         SMEM_BYTES);
    bahdanau_stage1<<<NBLK, NTHR, SMEM_BYTES>>>(q, keys, S);
    bahdanau_stage2<<<16, 512>>>((float*)d_out);
}